// round 16
// baseline (speedup 1.0000x reference)
#include <cuda_runtime.h>
#include <cuda_fp16.h>
#include <cstdint>

#define M_DIM 1024
#define N_DIM 512
#define K_DIM 512

#define BM 64
#define BN 64
#define KC 64
#define NCHUNK (K_DIM / KC)    // 8
#define NTHREADS 512

#define A_OFF 0
#define B_OFF 8192
#define CHUNK_BYTES 16384
#define SMEM_DYN (NCHUNK * CHUNK_BYTES)   // 128KB, whole K resident

// ---------------- helpers ----------------
__device__ __forceinline__ uint32_t smem_u32(const void* p) {
    uint32_t a;
    asm("{ .reg .u64 t; cvta.to.shared.u64 t, %1; cvt.u32.u64 %0, t; }"
        : "=r"(a) : "l"(p));
    return a;
}
__device__ __forceinline__ uint32_t sw128(uint32_t off) {
    return off ^ ((off >> 3) & 0x70);
}
__device__ __forceinline__ void ldsm4(uint32_t* r, uint32_t addr) {
    asm volatile("ldmatrix.sync.aligned.m8n8.x4.shared.b16 {%0,%1,%2,%3}, [%4];"
                 : "=r"(r[0]), "=r"(r[1]), "=r"(r[2]), "=r"(r[3]) : "r"(addr));
}
__device__ __forceinline__ void mma_f16(float* c, const uint32_t* a, const uint32_t* b) {
    asm volatile(
        "mma.sync.aligned.m16n8k16.row.col.f32.f16.f16.f32 "
        "{%0,%1,%2,%3}, {%4,%5,%6,%7}, {%8,%9}, {%0,%1,%2,%3};"
        : "+f"(c[0]), "+f"(c[1]), "+f"(c[2]), "+f"(c[3])
        : "r"(a[0]), "r"(a[1]), "r"(a[2]), "r"(a[3]), "r"(b[0]), "r"(b[1]));
}
__device__ __forceinline__ uint32_t pack_hi(float a, float b) {
    __half2 h = __halves2half2(__float2half_rn(a), __float2half_rn(b));
    return *reinterpret_cast<uint32_t*>(&h);
}

// ---------------- fused kernel ----------------
__global__ __launch_bounds__(NTHREADS, 1)
void filp_kernel(const float* __restrict__ X,
                 const float* __restrict__ W,
                 const float* __restrict__ bias,
                 float* __restrict__ out)
{
    extern __shared__ char smem[];
    const uint32_t sbase = smem_u32(smem);

    const int tid  = threadIdx.x;
    const int lane = tid & 31;
    const int wid  = tid >> 5;           // 0..15
    const int wm   = (wid & 3) * 16;     // warp M offset
    const int wn   = (wid >> 2) * 16;    // warp N offset

    const int m0 = blockIdx.y * BM;
    const int n0 = blockIdx.x * BN;

    // bias prefetch: issued whole-kernel early
    const int nb = n0 + wn + (lane & 3) * 2;
    const float2 bb0 = *reinterpret_cast<const float2*>(bias + nb);
    const float2 bb1 = *reinterpret_cast<const float2*>(bias + nb + 8);

    // even/odd k accumulators: halves the HMMA RAW chain
    float acc[2][2][4];
    #pragma unroll
    for (int p = 0; p < 2; p++)
        #pragma unroll
        for (int b = 0; b < 2; b++)
            #pragma unroll
            for (int q = 0; q < 4; q++) acc[p][b][q] = 0.0f;

    const int arow_l  = lane & 15;
    const int ahalf16 = ((lane >> 4) & 1) * 16;
    const int brow_l  = (lane & 7) + ((lane & 16) ? 8 : 0);
    const int bhalf16 = ((lane >> 3) & 1) * 16;

    // per-warp constant address components
    const uint32_t ra      = (uint32_t)(wm + arow_l);
    const uint32_t a_base  = sbase + A_OFF + ra * 128;
    const uint32_t a_swx   = (ra & 7) << 4;
    const uint32_t rb      = (uint32_t)(wn + brow_l);
    const uint32_t b_base  = sbase + B_OFF + rb * 128;
    const uint32_t b_swx   = (rb & 7) << 4;

    // triple-buffered fragments (lookahead 2)
    uint32_t fa[3][4], fb[3][4];

    auto load_frags = [&](int ks, int pb) {
        const uint32_t coff = (uint32_t)(ks >> 2) * CHUNK_BYTES;
        const int sub = ks & 3;
        const uint32_t kb_a = (uint32_t)(sub * 32 + ahalf16);
        const uint32_t kb_b = (uint32_t)(sub * 32 + bhalf16);
        ldsm4(fa[pb], a_base + coff + (kb_a ^ a_swx));
        ldsm4(fb[pb], b_base + coff + (kb_b ^ b_swx));
    };

    auto ldg_chunk = [&](int c, float4* v) {
        const int kc = c * KC;
        #pragma unroll
        for (int i = 0; i < 4; i++) {
            int u = i * NTHREADS + tid;     // 0..2047
            int r  = (u >> 4) & 63;
            int cu = u & 15;
            if (u < 1024)
                v[i] = *reinterpret_cast<const float4*>(
                    X + (size_t)(m0 + r) * K_DIM + kc + cu * 4);
            else
                v[i] = *reinterpret_cast<const float4*>(
                    W + (size_t)(n0 + r) * K_DIM + kc + cu * 4);
        }
    };

    auto sts_chunk = [&](int c, const float4* v) {
        const int base = c * CHUNK_BYTES;
        #pragma unroll
        for (int i = 0; i < 4; i++) {
            int u = i * NTHREADS + tid;
            int r  = (u >> 4) & 63;
            int cu = u & 15;                 // 8B unit within 128B row
            uint32_t off = sw128((uint32_t)(r * 128 + cu * 8));
            uint2 hi;
            hi.x = pack_hi(v[i].x, v[i].y);
            hi.y = pack_hi(v[i].z, v[i].w);
            if (u < 1024)
                *reinterpret_cast<uint2*>(&smem[base + A_OFF + off]) = hi;
            else
                *reinterpret_cast<uint2*>(&smem[base + B_OFF + off]) = hi;
        }
    };

    // ---- load ENTIRE K into smem, high MLP, no intermediate barriers ----
    float4 vreg[2][4];
    ldg_chunk(0, vreg[0]);
    #pragma unroll
    for (int c = 0; c < NCHUNK; c++) {
        if (c + 1 < NCHUNK) ldg_chunk(c + 1, vreg[(c + 1) & 1]);
        sts_chunk(c, vreg[c & 1]);
    }
    __syncthreads();   // the ONLY barrier

    // ---- 32 k-steps straight through, frag triple-buffered (lookahead 2) ----
    load_frags(0, 0);
    load_frags(1, 1);
    #pragma unroll
    for (int ks = 0; ks < 32; ks++) {
        const int cur = ks % 3;
        if (ks < 30) load_frags(ks + 2, (ks + 2) % 3);
        const int p = ks & 1;
        mma_f16(acc[p][0], fa[cur], &fb[cur][0]);
        mma_f16(acc[p][1], fa[cur], &fb[cur][2]);
    }

    // ---- fused epilogue: out = x * wx + bias ; x from resident A tile ----
    // X[m][n] == A_smem[m-m0][k=n] (this CTA's n-range ⊂ resident k-range)
    const uint32_t achunk = sbase + (uint32_t)(n0 / KC) * CHUNK_BYTES + A_OFF;
    #pragma unroll
    for (int nt = 0; nt < 2; nt++) {
        const int rm0 = wm + (lane >> 2);
        const int cn  = wn + nt * 8 + (lane & 3) * 2;   // even -> 4B aligned
        const int m = m0 + rm0;
        const int n = n0 + cn;

        uint32_t xa0, xa1;
        asm volatile("ld.shared.b32 %0, [%1];" : "=r"(xa0)
                     : "r"(achunk + sw128((uint32_t)(rm0 * 128 + cn * 2))));
        asm volatile("ld.shared.b32 %0, [%1];" : "=r"(xa1)
                     : "r"(achunk + sw128((uint32_t)((rm0 + 8) * 128 + cn * 2))));
        float2 x0 = __half22float2(*reinterpret_cast<__half2*>(&xa0));
        float2 x1 = __half22float2(*reinterpret_cast<__half2*>(&xa1));

        float wx0 = acc[0][nt][0] + acc[1][nt][0];
        float wx1 = acc[0][nt][1] + acc[1][nt][1];
        float wx2 = acc[0][nt][2] + acc[1][nt][2];
        float wx3 = acc[0][nt][3] + acc[1][nt][3];

        const float2 bb = nt ? bb1 : bb0;
        float2 o0, o1;
        o0.x = fmaf(x0.x, wx0, bb.x);
        o0.y = fmaf(x0.y, wx1, bb.y);
        o1.x = fmaf(x1.x, wx2, bb.x);
        o1.y = fmaf(x1.y, wx3, bb.y);
        *reinterpret_cast<float2*>(out + (size_t)m * N_DIM + n) = o0;
        *reinterpret_cast<float2*>(out + (size_t)(m + 8) * N_DIM + n) = o1;
    }
}

// ---------------- launch ----------------
extern "C" void kernel_launch(void* const* d_in, const int* in_sizes, int n_in,
                              void* d_out, int out_size) {
    const float* x    = (const float*)d_in[0];   // (1024, 512)
    const float* w    = (const float*)d_in[1];   // (512, 512)
    const float* bias = (const float*)d_in[2];   // (512,)
    float* out        = (float*)d_out;           // (1024, 512)

    cudaFuncSetAttribute(filp_kernel, cudaFuncAttributeMaxDynamicSharedMemorySize, SMEM_DYN);

    dim3 grid(N_DIM / BN, M_DIM / BM);   // (8, 16) = 128 CTAs
    filp_kernel<<<grid, NTHREADS, SMEM_DYN>>>(x, w, bias, out);
}

// round 17
// speedup vs baseline: 1.2546x; 1.2546x over previous
#include <cuda_runtime.h>
#include <cuda_fp16.h>
#include <cstdint>

#define M_DIM 1024
#define N_DIM 512
#define K_DIM 512

#define BM 64
#define BN 64
#define KC 64
#define NCHUNK (K_DIM / KC)    // 8
#define NTHREADS 512

#define A_OFF 0
#define B_OFF 8192
#define CHUNK_BYTES 16384
#define SMEM_DYN (NCHUNK * CHUNK_BYTES)   // 128KB, whole K resident

// ---------------- helpers ----------------
__device__ __forceinline__ uint32_t smem_u32(const void* p) {
    uint32_t a;
    asm("{ .reg .u64 t; cvta.to.shared.u64 t, %1; cvt.u32.u64 %0, t; }"
        : "=r"(a) : "l"(p));
    return a;
}
__device__ __forceinline__ uint32_t sw128(uint32_t off) {
    return off ^ ((off >> 3) & 0x70);
}
__device__ __forceinline__ void ldsm4(uint32_t* r, uint32_t addr) {
    asm volatile("ldmatrix.sync.aligned.m8n8.x4.shared.b16 {%0,%1,%2,%3}, [%4];"
                 : "=r"(r[0]), "=r"(r[1]), "=r"(r[2]), "=r"(r[3]) : "r"(addr));
}
__device__ __forceinline__ void mma_f16(float* c, const uint32_t* a, const uint32_t* b) {
    asm volatile(
        "mma.sync.aligned.m16n8k16.row.col.f32.f16.f16.f32 "
        "{%0,%1,%2,%3}, {%4,%5,%6,%7}, {%8,%9}, {%0,%1,%2,%3};"
        : "+f"(c[0]), "+f"(c[1]), "+f"(c[2]), "+f"(c[3])
        : "r"(a[0]), "r"(a[1]), "r"(a[2]), "r"(a[3]), "r"(b[0]), "r"(b[1]));
}
// single-instruction fp32x2 -> fp16x2 pack (F2FP.PACK)
__device__ __forceinline__ uint32_t pack2(float a, float b) {
    __half2 h = __floats2half2_rn(a, b);
    return *reinterpret_cast<uint32_t*>(&h);
}

// ---------------- fused kernel ----------------
__global__ __launch_bounds__(NTHREADS, 1)
void filp_kernel(const float* __restrict__ X,
                 const float* __restrict__ W,
                 const float* __restrict__ bias,
                 float* __restrict__ out)
{
    extern __shared__ char smem[];
    const uint32_t sbase = smem_u32(smem);

    const int tid  = threadIdx.x;
    const int lane = tid & 31;
    const int wid  = tid >> 5;           // 0..15
    const int wm   = (wid & 3) * 16;     // warp M offset
    const int wn   = (wid >> 2) * 16;    // warp N offset

    const int m0 = blockIdx.y * BM;
    const int n0 = blockIdx.x * BN;

    // bias prefetch: issued whole-kernel early, consumed in epilogue
    const int nb = n0 + wn + (lane & 3) * 2;
    const float2 bb0 = *reinterpret_cast<const float2*>(bias + nb);
    const float2 bb1 = *reinterpret_cast<const float2*>(bias + nb + 8);

    // even/odd k accumulators: halves the HMMA RAW chain
    float acc[2][2][4];
    #pragma unroll
    for (int p = 0; p < 2; p++)
        #pragma unroll
        for (int b = 0; b < 2; b++)
            #pragma unroll
            for (int q = 0; q < 4; q++) acc[p][b][q] = 0.0f;

    const int arow_l  = lane & 15;
    const int ahalf16 = ((lane >> 4) & 1) * 16;
    const int brow_l  = (lane & 7) + ((lane & 16) ? 8 : 0);
    const int bhalf16 = ((lane >> 3) & 1) * 16;

    uint32_t fa[2][4], fb[2][4];

    auto load_frags = [&](uint32_t stb, int s, int pb) {
        const uint32_t kb_a = (uint32_t)(s * 32 + ahalf16);
        const uint32_t kb_b = (uint32_t)(s * 32 + bhalf16);
        const uint32_t ra = (uint32_t)(wm + arow_l);
        const uint32_t ao = ra * 128 + (kb_a ^ ((ra & 7) << 4));
        ldsm4(fa[pb], stb + A_OFF + ao);
        const uint32_t rb = (uint32_t)(wn + brow_l);
        const uint32_t bo = rb * 128 + (kb_b ^ ((rb & 7) << 4));
        ldsm4(fb[pb], stb + B_OFF + bo);
    };

    auto ldg_chunk = [&](int c, float4* v) {
        const int kc = c * KC;
        #pragma unroll
        for (int i = 0; i < 4; i++) {
            int u = i * NTHREADS + tid;     // 0..2047
            int r  = (u >> 4) & 63;
            int cu = u & 15;
            if (u < 1024)
                v[i] = *reinterpret_cast<const float4*>(
                    X + (size_t)(m0 + r) * K_DIM + kc + cu * 4);
            else
                v[i] = *reinterpret_cast<const float4*>(
                    W + (size_t)(n0 + r) * K_DIM + kc + cu * 4);
        }
    };

    auto sts_chunk = [&](int c, const float4* v) {
        const int base = c * CHUNK_BYTES;
        #pragma unroll
        for (int i = 0; i < 4; i++) {
            int u = i * NTHREADS + tid;
            int r  = (u >> 4) & 63;
            int cu = u & 15;                 // 8B unit within 128B row
            uint32_t off = sw128((uint32_t)(r * 128 + cu * 8));
            uint2 hi;
            hi.x = pack2(v[i].x, v[i].y);
            hi.y = pack2(v[i].z, v[i].w);
            if (u < 1024)
                *reinterpret_cast<uint2*>(&smem[base + A_OFF + off]) = hi;
            else
                *reinterpret_cast<uint2*>(&smem[base + B_OFF + off]) = hi;
        }
    };

    // ---- load ENTIRE K into smem: 3-deep LDG buffering hides L2 latency ----
    float4 vreg[3][4];
    ldg_chunk(0, vreg[0]);
    ldg_chunk(1, vreg[1]);
    #pragma unroll
    for (int c = 0; c < NCHUNK; c++) {
        if (c + 2 < NCHUNK) ldg_chunk(c + 2, vreg[(c + 2) % 3]);
        sts_chunk(c, vreg[c % 3]);
    }
    __syncthreads();   // the ONLY barrier

    // ---- 32 k-steps straight through, frag + acc double-buffered ----
    load_frags(sbase, 0, 0);
    #pragma unroll
    for (int c = 0; c < NCHUNK; c++) {
        #pragma unroll
        for (int s = 0; s < 4; s++) {
            const int ks  = c * 4 + s;
            const int cur = ks & 1;
            if (ks < 31) {
                const int nk = ks + 1;
                load_frags(sbase + (uint32_t)(nk >> 2) * CHUNK_BYTES, nk & 3, cur ^ 1);
            }
            mma_f16(acc[cur][0], fa[cur], &fb[cur][0]);
            mma_f16(acc[cur][1], fa[cur], &fb[cur][2]);
        }
    }

    // ---- fused epilogue: out = x * wx + bias ----
    // x is read from the RESIDENT A tile: X[m][n] == A_smem[m-m0][k=n]
    // (this CTA's n-range lies inside its resident k-range 0..511)
    const uint32_t achunk = sbase + (uint32_t)(n0 / KC) * CHUNK_BYTES + A_OFF;
    #pragma unroll
    for (int nt = 0; nt < 2; nt++) {
        const int rm0 = wm + (lane >> 2);
        const int cn  = wn + nt * 8 + (lane & 3) * 2;   // even -> 4B aligned
        const int m = m0 + rm0;
        const int n = n0 + cn;

        uint32_t xa0, xa1;
        asm volatile("ld.shared.b32 %0, [%1];" : "=r"(xa0)
                     : "r"(achunk + sw128((uint32_t)(rm0 * 128 + cn * 2))));
        asm volatile("ld.shared.b32 %0, [%1];" : "=r"(xa1)
                     : "r"(achunk + sw128((uint32_t)((rm0 + 8) * 128 + cn * 2))));
        float2 x0 = __half22float2(*reinterpret_cast<__half2*>(&xa0));
        float2 x1 = __half22float2(*reinterpret_cast<__half2*>(&xa1));

        float wx0 = acc[0][nt][0] + acc[1][nt][0];
        float wx1 = acc[0][nt][1] + acc[1][nt][1];
        float wx2 = acc[0][nt][2] + acc[1][nt][2];
        float wx3 = acc[0][nt][3] + acc[1][nt][3];

        const float2 bb = nt ? bb1 : bb0;
        float2 o0, o1;
        o0.x = fmaf(x0.x, wx0, bb.x);
        o0.y = fmaf(x0.y, wx1, bb.y);
        o1.x = fmaf(x1.x, wx2, bb.x);
        o1.y = fmaf(x1.y, wx3, bb.y);
        *reinterpret_cast<float2*>(out + (size_t)m * N_DIM + n) = o0;
        *reinterpret_cast<float2*>(out + (size_t)(m + 8) * N_DIM + n) = o1;
    }
}

// ---------------- launch ----------------
extern "C" void kernel_launch(void* const* d_in, const int* in_sizes, int n_in,
                              void* d_out, int out_size) {
    const float* x    = (const float*)d_in[0];   // (1024, 512)
    const float* w    = (const float*)d_in[1];   // (512, 512)
    const float* bias = (const float*)d_in[2];   // (512,)
    float* out        = (float*)d_out;           // (1024, 512)

    cudaFuncSetAttribute(filp_kernel, cudaFuncAttributeMaxDynamicSharedMemorySize, SMEM_DYN);

    dim3 grid(N_DIM / BN, M_DIM / BM);   // (8, 16) = 128 CTAs
    filp_kernel<<<grid, NTHREADS, SMEM_DYN>>>(x, w, bias, out);
}